// round 11
// baseline (speedup 1.0000x reference)
#include <cuda_runtime.h>

#define BATCH  16
#define SEQ    1024
#define HDIM   768
#define NHEADS 12
#define HD     64
#define MTOK   (BATCH*SEQ)      /* 16384 */
#define QKVN   (3*HDIM)         /* 2304  */

// ------------------------- device scratch (no alloc rule) -------------------
__device__ __align__(256) float g_Q[BATCH*NHEADS*SEQ*HD];
__device__ __align__(256) float g_K[BATCH*NHEADS*SEQ*HD];
__device__ __align__(256) float g_V[BATCH*NHEADS*SEQ*HD];
__device__ __align__(256) float g_AttO[MTOK*HDIM];

// Fast exp2 on (-inf, 0]: degree-6 poly + exponent bits. No MUFU.
__device__ __forceinline__ float exp2f_fast(float x) {
    x = fmaxf(x, -125.0f);
    float t = floorf(x);
    float f = x - t;
    float p = 1.5403530e-4f;
    p = fmaf(p, f, 1.3333558e-3f);
    p = fmaf(p, f, 9.6181291e-3f);
    p = fmaf(p, f, 5.5504109e-2f);
    p = fmaf(p, f, 2.4022651e-1f);
    p = fmaf(p, f, 6.9314718e-1f);
    p = fmaf(p, f, 1.0f);
    int e = (int)t;
    return p * __int_as_float((e + 127) << 23);
}

// ---------------------------------------------------------------------------
// SGEMM (round-9/10 verified, FROZEN): C[M,Ncols] = A[M,768] @ W[768,Ncols] + bias
// ---------------------------------------------------------------------------
#define KB     16
#define NCHUNK (HDIM / KB)      /* 48 */

template<int MODE>
__global__ __launch_bounds__(256)
void sgemm_kernel(const float* __restrict__ A, const float* __restrict__ W,
                  const float* __restrict__ bias, float* __restrict__ out,
                  int Ncols)
{
    __shared__ float As[2][KB][132];
    __shared__ float Bs[2][KB][128];

    const int tid = threadIdx.x;
    const int m0  = blockIdx.y * 128;
    const int c0  = blockIdx.x * 128;
    const int ty  = tid >> 4;
    const int tx  = tid & 15;

    const float* Ap = (MODE == 0) ? A : g_AttO;

    const int ar = tid >> 1;
    const int ac = (tid & 1) * 8;
    const int br = tid >> 5;
    const int bc = (tid & 31) * 4;

    float acc[8][8];
#pragma unroll
    for (int i = 0; i < 8; i++)
#pragma unroll
        for (int j = 0; j < 8; j++) acc[i][j] = 0.f;

    {
        float4 a0 = *reinterpret_cast<const float4*>(Ap + (size_t)(m0 + ar) * HDIM + ac);
        float4 a1 = *reinterpret_cast<const float4*>(Ap + (size_t)(m0 + ar) * HDIM + ac + 4);
        float4 b0 = *reinterpret_cast<const float4*>(W + (size_t)br * Ncols + c0 + bc);
        float4 b1 = *reinterpret_cast<const float4*>(W + (size_t)(br + 8) * Ncols + c0 + bc);
        As[0][ac + 0][ar] = a0.x; As[0][ac + 1][ar] = a0.y;
        As[0][ac + 2][ar] = a0.z; As[0][ac + 3][ar] = a0.w;
        As[0][ac + 4][ar] = a1.x; As[0][ac + 5][ar] = a1.y;
        As[0][ac + 6][ar] = a1.z; As[0][ac + 7][ar] = a1.w;
        *reinterpret_cast<float4*>(&Bs[0][br][bc])     = b0;
        *reinterpret_cast<float4*>(&Bs[0][br + 8][bc]) = b1;
    }
    __syncthreads();

    for (int ch = 0; ch < NCHUNK; ch++) {
        const int buf = ch & 1;
        float4 a0, a1, b0, b1;
        if (ch + 1 < NCHUNK) {
            const int kb = (ch + 1) * KB;
            a0 = *reinterpret_cast<const float4*>(Ap + (size_t)(m0 + ar) * HDIM + kb + ac);
            a1 = *reinterpret_cast<const float4*>(Ap + (size_t)(m0 + ar) * HDIM + kb + ac + 4);
            b0 = *reinterpret_cast<const float4*>(W + (size_t)(kb + br) * Ncols + c0 + bc);
            b1 = *reinterpret_cast<const float4*>(W + (size_t)(kb + br + 8) * Ncols + c0 + bc);
        }

#pragma unroll
        for (int k = 0; k < KB; k++) {
            float a[8], b[8];
            *(float4*)&a[0] = *(const float4*)&As[buf][k][ty * 8];
            *(float4*)&a[4] = *(const float4*)&As[buf][k][ty * 8 + 4];
            *(float4*)&b[0] = *(const float4*)&Bs[buf][k][tx * 8];
            *(float4*)&b[4] = *(const float4*)&Bs[buf][k][tx * 8 + 4];
#pragma unroll
            for (int i = 0; i < 8; i++)
#pragma unroll
                for (int j = 0; j < 8; j++) acc[i][j] = fmaf(a[i], b[j], acc[i][j]);
        }

        if (ch + 1 < NCHUNK) {
            const int nb = buf ^ 1;
            As[nb][ac + 0][ar] = a0.x; As[nb][ac + 1][ar] = a0.y;
            As[nb][ac + 2][ar] = a0.z; As[nb][ac + 3][ar] = a0.w;
            As[nb][ac + 4][ar] = a1.x; As[nb][ac + 5][ar] = a1.y;
            As[nb][ac + 6][ar] = a1.z; As[nb][ac + 7][ar] = a1.w;
            *reinterpret_cast<float4*>(&Bs[nb][br][bc])     = b0;
            *reinterpret_cast<float4*>(&Bs[nb][br + 8][bc]) = b1;
        }
        __syncthreads();
    }

    if (MODE == 0) {
        const int cbase = c0 + tx * 8;
        const int part  = cbase / HDIM;
        const int cc    = cbase - part * HDIM;
        const int h     = cc >> 6;
        const int dbase = cc & 63;
        float* dst = (part == 0) ? g_Q : (part == 1 ? g_K : g_V);
#pragma unroll
        for (int i = 0; i < 8; i++) {
            int m = m0 + ty * 8 + i;
            int bi = m >> 10, n = m & (SEQ - 1);
            float* p = dst + ((size_t)(bi * NHEADS + h) * SEQ + n) * HD + dbase;
#pragma unroll
            for (int j = 0; j < 8; j++) p[j] = acc[i][j] + bias[cbase + j];
        }
    } else {
#pragma unroll
        for (int i = 0; i < 8; i++) {
            int m = m0 + ty * 8 + i;
            float* p = out + (size_t)m * HDIM + c0 + tx * 8;
#pragma unroll
            for (int j = 0; j < 8; j++) p[j] = acc[i][j] + bias[c0 + tx * 8 + j];
        }
    }
}

// ---------------------------------------------------------------------------
// Flash attention, 128 threads (4 warps), 64x64 tile, 8x4 microtile.
// Qs [d][q] (pre-scaled). Ks triple duty:
//   K phase:  [d][kv] XOR-swizzled  (group = ((kv>>2)+(d>>2))&15)
//   P phase:  [kv][q] XOR-swizzled  (group = ((q>>2)+(kv>>2))&15)  <-- NEW
// PV inner loop now 3 LDS / 32 FMA (was 9/32): pa via 2 broadcast LDS.128.
// Smem = 3*64*64*4 = 48KB.
// ---------------------------------------------------------------------------
__global__ __launch_bounds__(128)
void attn_kernel()
{
    __shared__ float Qs[64][64];
    __shared__ float Ks[64][64];
    __shared__ float Vs[64][64];

    const int tid = threadIdx.x;
    const int tx  = tid & 15;      // col group: cols tx*4..+3
    const int ty  = tid >> 4;      // row group: rows ty*8..+7
    const int b   = blockIdx.z, h = blockIdx.y;
    const int q0  = blockIdx.x * 64;

    const float* Qg = g_Q + (size_t)((b * NHEADS + h) * SEQ + q0) * HD;
    const float* Kg = g_K + (size_t)((b * NHEADS + h) * SEQ) * HD;
    const float* Vg = g_V + (size_t)((b * NHEADS + h) * SEQ) * HD;

    const float QSCALE = 0.125f * 1.4426950408889634f;  // log2e / sqrt(64)
    float* ksf = &Ks[0][0];

    // Q staging: transposed [d][q], pre-scaled (one-time)
    for (int f = tid; f < 1024; f += 128) {
        int r = f >> 4, c4 = (f & 15) << 2;
        float4 v = *reinterpret_cast<const float4*>(Qg + r * HD + c4);
        Qs[c4 + 0][r] = v.x * QSCALE; Qs[c4 + 1][r] = v.y * QSCALE;
        Qs[c4 + 2][r] = v.z * QSCALE; Qs[c4 + 3][r] = v.w * QSCALE;
    }

    float o[8][4], mrow[8], lrow[8];
#pragma unroll
    for (int i = 0; i < 8; i++) {
        mrow[i] = -1e30f; lrow[i] = 0.f;
#pragma unroll
        for (int j = 0; j < 4; j++) o[i][j] = 0.f;
    }

    for (int kt = 0; kt < SEQ / 64; kt++) {
        __syncthreads();                       // prev iter done with Ks/Vs
        const float* Kt = Kg + (size_t)kt * 64 * HD;
        const float* Vt = Vg + (size_t)kt * 64 * HD;
        for (int f = tid; f < 1024; f += 128) {
            int r  = f >> 4;                   // kv row 0..63
            int c4 = (f & 15) << 2;            // d chunk base
            float4 kv = *reinterpret_cast<const float4*>(Kt + r * HD + c4);
            int sg   = ((r >> 2) + (c4 >> 2)) & 15;
            int base = sg * 4 + (r & 3);
            ksf[(c4 + 0) * 64 + base] = kv.x;
            ksf[(c4 + 1) * 64 + base] = kv.y;
            ksf[(c4 + 2) * 64 + base] = kv.z;
            ksf[(c4 + 3) * 64 + base] = kv.w;
            float4 vv = *reinterpret_cast<const float4*>(Vt + r * HD + c4);
            *reinterpret_cast<float4*>(&Vs[r][c4]) = vv;
        }
        __syncthreads();

        // S = Qscaled @ K^T  (8x4 per thread)
        float s[8][4];
#pragma unroll
        for (int i = 0; i < 8; i++)
#pragma unroll
            for (int j = 0; j < 4; j++) s[i][j] = 0.f;
#pragma unroll 4
        for (int d = 0; d < 64; d++) {
            float qa[8], kb[4];
            *(float4*)&qa[0] = *(const float4*)&Qs[d][ty * 8];
            *(float4*)&qa[4] = *(const float4*)&Qs[d][ty * 8 + 4];
            int g = (tx + (d >> 2)) & 15;
            *(float4*)&kb[0] = *(const float4*)&ksf[d * 64 + g * 4];
#pragma unroll
            for (int i = 0; i < 8; i++)
#pragma unroll
                for (int j = 0; j < 4; j++) s[i][j] = fmaf(qa[i], kb[j], s[i][j]);
        }

        // online softmax (row stats across the 16 lanes sharing ty)
#pragma unroll
        for (int i = 0; i < 8; i++) {
            float mx = fmaxf(fmaxf(s[i][0], s[i][1]), fmaxf(s[i][2], s[i][3]));
            mx = fmaxf(mx, __shfl_xor_sync(0xffffffffu, mx, 1));
            mx = fmaxf(mx, __shfl_xor_sync(0xffffffffu, mx, 2));
            mx = fmaxf(mx, __shfl_xor_sync(0xffffffffu, mx, 4));
            mx = fmaxf(mx, __shfl_xor_sync(0xffffffffu, mx, 8));
            float mnew = fmaxf(mrow[i], mx);
            float corr = exp2f_fast(mrow[i] - mnew);
            float rs = 0.f;
#pragma unroll
            for (int j = 0; j < 4; j++) {
                float p = exp2f_fast(s[i][j] - mnew);
                s[i][j] = p; rs += p;
            }
            rs += __shfl_xor_sync(0xffffffffu, rs, 1);
            rs += __shfl_xor_sync(0xffffffffu, rs, 2);
            rs += __shfl_xor_sync(0xffffffffu, rs, 4);
            rs += __shfl_xor_sync(0xffffffffu, rs, 8);
            lrow[i] = lrow[i] * corr + rs;
            mrow[i] = mnew;
#pragma unroll
            for (int j = 0; j < 4; j++) o[i][j] *= corr;
        }

        __syncthreads();                       // done reading Ks as K
        // P^T staged into Ks buffer: Pt[kv][q] swizzled, 8 x STS.128.
        // kv = tx*4+j (kv>>2 == tx), q chunks {0..3} -> 2ty, {4..7} -> 2ty+1.
#pragma unroll
        for (int j = 0; j < 4; j++) {
            const int kv = tx * 4 + j;
            const int g0 = ((2 * ty)     + tx) & 15;
            const int g1 = ((2 * ty + 1) + tx) & 15;
            float4 p0, p1;
            p0.x = s[0][j]; p0.y = s[1][j]; p0.z = s[2][j]; p0.w = s[3][j];
            p1.x = s[4][j]; p1.y = s[5][j]; p1.z = s[6][j]; p1.w = s[7][j];
            *reinterpret_cast<float4*>(&ksf[kv * 64 + g0 * 4]) = p0;
            *reinterpret_cast<float4*>(&ksf[kv * 64 + g1 * 4]) = p1;
        }
        __syncthreads();

        // O += P @ V  (3 LDS / 32 FMA per k-step)
#pragma unroll 4
        for (int k = 0; k < 64; k++) {
            float pa[8], vb[4];
            const int g0 = ((2 * ty)     + (k >> 2)) & 15;
            const int g1 = ((2 * ty + 1) + (k >> 2)) & 15;
            *(float4*)&pa[0] = *(const float4*)&ksf[k * 64 + g0 * 4];
            *(float4*)&pa[4] = *(const float4*)&ksf[k * 64 + g1 * 4];
            *(float4*)&vb[0] = *(const float4*)&Vs[k][tx * 4];
#pragma unroll
            for (int i = 0; i < 8; i++)
#pragma unroll
                for (int j = 0; j < 4; j++) o[i][j] = fmaf(pa[i], vb[j], o[i][j]);
        }
    }

    // normalize + write [B, N, H] (heads concatenated)
#pragma unroll
    for (int i = 0; i < 8; i++) {
        float inv = 1.f / lrow[i];
        int n = q0 + ty * 8 + i;
        float4 v;
        v.x = o[i][0] * inv; v.y = o[i][1] * inv;
        v.z = o[i][2] * inv; v.w = o[i][3] * inv;
        *reinterpret_cast<float4*>(
            g_AttO + (size_t)(b * SEQ + n) * HDIM + h * HD + tx * 4) = v;
    }
}

// ---------------------------------------------------------------------------
extern "C" void kernel_launch(void* const* d_in, const int* in_sizes, int n_in,
                              void* d_out, int out_size)
{
    const float* x     = (const float*)d_in[0];
    const float* w_qkv = (const float*)d_in[1];
    const float* b_qkv = (const float*)d_in[2];
    const float* w_out = (const float*)d_in[3];
    const float* b_out = (const float*)d_in[4];
    float* out = (float*)d_out;
    (void)in_sizes; (void)n_in; (void)out_size;

    dim3 g1(QKVN / 128, MTOK / 128);
    sgemm_kernel<0><<<g1, 256>>>(x, w_qkv, b_qkv, nullptr, QKVN);

    dim3 g2(SEQ / 64, NHEADS, BATCH);
    attn_kernel<<<g2, 128>>>();

    dim3 g3(HDIM / 128, MTOK / 128);
    sgemm_kernel<1><<<g3, 256>>>(g_AttO, w_out, b_out, out, HDIM);
}

// round 13
// speedup vs baseline: 1.0110x; 1.0110x over previous
#include <cuda_runtime.h>

#define BATCH  16
#define SEQ    1024
#define HDIM   768
#define NHEADS 12
#define HD     64
#define MTOK   (BATCH*SEQ)      /* 16384 */
#define QKVN   (3*HDIM)         /* 2304  */

// ------------------------- device scratch (no alloc rule) -------------------
__device__ __align__(256) float g_Q[BATCH*NHEADS*SEQ*HD];
__device__ __align__(256) float g_K[BATCH*NHEADS*SEQ*HD];
__device__ __align__(256) float g_V[BATCH*NHEADS*SEQ*HD];
__device__ __align__(256) float g_AttO[MTOK*HDIM];

// Fast exp2 on (-inf, 0]: degree-6 poly + exponent bits. No MUFU.
__device__ __forceinline__ float exp2f_fast(float x) {
    x = fmaxf(x, -125.0f);
    float t = floorf(x);
    float f = x - t;
    float p = 1.5403530e-4f;
    p = fmaf(p, f, 1.3333558e-3f);
    p = fmaf(p, f, 9.6181291e-3f);
    p = fmaf(p, f, 5.5504109e-2f);
    p = fmaf(p, f, 2.4022651e-1f);
    p = fmaf(p, f, 6.9314718e-1f);
    p = fmaf(p, f, 1.0f);
    int e = (int)t;
    return p * __int_as_float((e + 127) << 23);
}

// ---------------------------------------------------------------------------
// SGEMM: C[M,Ncols] = A[M,768] @ W[768,Ncols] + bias
// 64x128 CTA tile, 128 threads (8x8 microtile), KB=16 double-buffered
// with register prefetch. ~16.3K regs/CTA -> 4 CTAs/SM = 32 warps (occ ~50%,
// was 2 CTAs/24.4% at the 128x128/256-thr shape).
// MODE 0: A = x, scatter into g_Q/g_K/g_V head-major. MODE 1: dense out.
// ---------------------------------------------------------------------------
#define KB     16
#define NCHUNK (HDIM / KB)      /* 48 */

template<int MODE>
__global__ __launch_bounds__(128)
void sgemm_kernel(const float* __restrict__ A, const float* __restrict__ W,
                  const float* __restrict__ bias, float* __restrict__ out,
                  int Ncols)
{
    __shared__ float As[2][KB][68];    // transposed [k][m], padded
    __shared__ float Bs[2][KB][128];   // natural [k][n]

    const int tid = threadIdx.x;
    const int m0  = blockIdx.y * 64;
    const int c0  = blockIdx.x * 128;
    const int ty  = tid >> 4;          // 0..7  -> rows ty*8..
    const int tx  = tid & 15;          // 0..15 -> cols tx*8..

    const float* Ap = (MODE == 0) ? A : g_AttO;

    // loader lanes: A = 2 float4 (one row, 16 k), B = 4 float4 (4 rows)
    const int ar = tid >> 1;           // 0..63
    const int ac = (tid & 1) * 8;      // 0 or 8
    const int br = tid >> 5;           // 0..3  (+4,+8,+12)
    const int bc = (tid & 31) * 4;     // 0..124

    float acc[8][8];
#pragma unroll
    for (int i = 0; i < 8; i++)
#pragma unroll
        for (int j = 0; j < 8; j++) acc[i][j] = 0.f;

    // ---- prologue: chunk 0 ----
    {
        float4 a0 = *reinterpret_cast<const float4*>(Ap + (size_t)(m0 + ar) * HDIM + ac);
        float4 a1 = *reinterpret_cast<const float4*>(Ap + (size_t)(m0 + ar) * HDIM + ac + 4);
        As[0][ac + 0][ar] = a0.x; As[0][ac + 1][ar] = a0.y;
        As[0][ac + 2][ar] = a0.z; As[0][ac + 3][ar] = a0.w;
        As[0][ac + 4][ar] = a1.x; As[0][ac + 5][ar] = a1.y;
        As[0][ac + 6][ar] = a1.z; As[0][ac + 7][ar] = a1.w;
#pragma unroll
        for (int r = 0; r < 4; r++) {
            float4 bv = *reinterpret_cast<const float4*>(
                W + (size_t)(br + r * 4) * Ncols + c0 + bc);
            *reinterpret_cast<float4*>(&Bs[0][br + r * 4][bc]) = bv;
        }
    }
    __syncthreads();

    for (int ch = 0; ch < NCHUNK; ch++) {
        const int buf = ch & 1;
        float4 a0, a1, b0, b1, b2, b3;
        if (ch + 1 < NCHUNK) {
            const int kb = (ch + 1) * KB;
            a0 = *reinterpret_cast<const float4*>(Ap + (size_t)(m0 + ar) * HDIM + kb + ac);
            a1 = *reinterpret_cast<const float4*>(Ap + (size_t)(m0 + ar) * HDIM + kb + ac + 4);
            b0 = *reinterpret_cast<const float4*>(W + (size_t)(kb + br +  0) * Ncols + c0 + bc);
            b1 = *reinterpret_cast<const float4*>(W + (size_t)(kb + br +  4) * Ncols + c0 + bc);
            b2 = *reinterpret_cast<const float4*>(W + (size_t)(kb + br +  8) * Ncols + c0 + bc);
            b3 = *reinterpret_cast<const float4*>(W + (size_t)(kb + br + 12) * Ncols + c0 + bc);
        }

#pragma unroll
        for (int k = 0; k < KB; k++) {
            float a[8], b[8];
            *(float4*)&a[0] = *(const float4*)&As[buf][k][ty * 8];
            *(float4*)&a[4] = *(const float4*)&As[buf][k][ty * 8 + 4];
            *(float4*)&b[0] = *(const float4*)&Bs[buf][k][tx * 8];
            *(float4*)&b[4] = *(const float4*)&Bs[buf][k][tx * 8 + 4];
#pragma unroll
            for (int i = 0; i < 8; i++)
#pragma unroll
                for (int j = 0; j < 8; j++) acc[i][j] = fmaf(a[i], b[j], acc[i][j]);
        }

        if (ch + 1 < NCHUNK) {
            const int nb = buf ^ 1;
            As[nb][ac + 0][ar] = a0.x; As[nb][ac + 1][ar] = a0.y;
            As[nb][ac + 2][ar] = a0.z; As[nb][ac + 3][ar] = a0.w;
            As[nb][ac + 4][ar] = a1.x; As[nb][ac + 5][ar] = a1.y;
            As[nb][ac + 6][ar] = a1.z; As[nb][ac + 7][ar] = a1.w;
            *reinterpret_cast<float4*>(&Bs[nb][br +  0][bc]) = b0;
            *reinterpret_cast<float4*>(&Bs[nb][br +  4][bc]) = b1;
            *reinterpret_cast<float4*>(&Bs[nb][br +  8][bc]) = b2;
            *reinterpret_cast<float4*>(&Bs[nb][br + 12][bc]) = b3;
        }
        __syncthreads();
    }

    if (MODE == 0) {
        const int cbase = c0 + tx * 8;
        const int part  = cbase / HDIM;                 // 0=Q 1=K 2=V
        const int cc    = cbase - part * HDIM;
        const int h     = cc >> 6;
        const int dbase = cc & 63;
        float* dst = (part == 0) ? g_Q : (part == 1 ? g_K : g_V);
#pragma unroll
        for (int i = 0; i < 8; i++) {
            int m = m0 + ty * 8 + i;
            int bi = m >> 10, n = m & (SEQ - 1);
            float* p = dst + ((size_t)(bi * NHEADS + h) * SEQ + n) * HD + dbase;
#pragma unroll
            for (int j = 0; j < 8; j++) p[j] = acc[i][j] + bias[cbase + j];
        }
    } else {
#pragma unroll
        for (int i = 0; i < 8; i++) {
            int m = m0 + ty * 8 + i;
            float* p = out + (size_t)m * HDIM + c0 + tx * 8;
#pragma unroll
            for (int j = 0; j < 8; j++) p[j] = acc[i][j] + bias[c0 + tx * 8 + j];
        }
    }
}

// ---------------------------------------------------------------------------
// Flash attention (round-10/11 verified, FROZEN): 128 threads, 64x64 tile,
// 8x4 microtile, MUFU-free softmax, swizzled K/P staging.
// ---------------------------------------------------------------------------
__global__ __launch_bounds__(128)
void attn_kernel()
{
    __shared__ float Qs[64][64];
    __shared__ float Ks[64][64];
    __shared__ float Vs[64][64];

    const int tid = threadIdx.x;
    const int tx  = tid & 15;
    const int ty  = tid >> 4;
    const int b   = blockIdx.z, h = blockIdx.y;
    const int q0  = blockIdx.x * 64;

    const float* Qg = g_Q + (size_t)((b * NHEADS + h) * SEQ + q0) * HD;
    const float* Kg = g_K + (size_t)((b * NHEADS + h) * SEQ) * HD;
    const float* Vg = g_V + (size_t)((b * NHEADS + h) * SEQ) * HD;

    const float QSCALE = 0.125f * 1.4426950408889634f;
    float* ksf = &Ks[0][0];

    for (int f = tid; f < 1024; f += 128) {
        int r = f >> 4, c4 = (f & 15) << 2;
        float4 v = *reinterpret_cast<const float4*>(Qg + r * HD + c4);
        Qs[c4 + 0][r] = v.x * QSCALE; Qs[c4 + 1][r] = v.y * QSCALE;
        Qs[c4 + 2][r] = v.z * QSCALE; Qs[c4 + 3][r] = v.w * QSCALE;
    }

    float o[8][4], mrow[8], lrow[8];
#pragma unroll
    for (int i = 0; i < 8; i++) {
        mrow[i] = -1e30f; lrow[i] = 0.f;
#pragma unroll
        for (int j = 0; j < 4; j++) o[i][j] = 0.f;
    }

    for (int kt = 0; kt < SEQ / 64; kt++) {
        __syncthreads();
        const float* Kt = Kg + (size_t)kt * 64 * HD;
        const float* Vt = Vg + (size_t)kt * 64 * HD;
        for (int f = tid; f < 1024; f += 128) {
            int r  = f >> 4;
            int c4 = (f & 15) << 2;
            float4 kv = *reinterpret_cast<const float4*>(Kt + r * HD + c4);
            int sg   = ((r >> 2) + (c4 >> 2)) & 15;
            int base = sg * 4 + (r & 3);
            ksf[(c4 + 0) * 64 + base] = kv.x;
            ksf[(c4 + 1) * 64 + base] = kv.y;
            ksf[(c4 + 2) * 64 + base] = kv.z;
            ksf[(c4 + 3) * 64 + base] = kv.w;
            float4 vv = *reinterpret_cast<const float4*>(Vt + r * HD + c4);
            *reinterpret_cast<float4*>(&Vs[r][c4]) = vv;
        }
        __syncthreads();

        float s[8][4];
#pragma unroll
        for (int i = 0; i < 8; i++)
#pragma unroll
            for (int j = 0; j < 4; j++) s[i][j] = 0.f;
#pragma unroll 4
        for (int d = 0; d < 64; d++) {
            float qa[8], kb[4];
            *(float4*)&qa[0] = *(const float4*)&Qs[d][ty * 8];
            *(float4*)&qa[4] = *(const float4*)&Qs[d][ty * 8 + 4];
            int g = (tx + (d >> 2)) & 15;
            *(float4*)&kb[0] = *(const float4*)&ksf[d * 64 + g * 4];
#pragma unroll
            for (int i = 0; i < 8; i++)
#pragma unroll
                for (int j = 0; j < 4; j++) s[i][j] = fmaf(qa[i], kb[j], s[i][j]);
        }

#pragma unroll
        for (int i = 0; i < 8; i++) {
            float mx = fmaxf(fmaxf(s[i][0], s[i][1]), fmaxf(s[i][2], s[i][3]));
            mx = fmaxf(mx, __shfl_xor_sync(0xffffffffu, mx, 1));
            mx = fmaxf(mx, __shfl_xor_sync(0xffffffffu, mx, 2));
            mx = fmaxf(mx, __shfl_xor_sync(0xffffffffu, mx, 4));
            mx = fmaxf(mx, __shfl_xor_sync(0xffffffffu, mx, 8));
            float mnew = fmaxf(mrow[i], mx);
            float corr = exp2f_fast(mrow[i] - mnew);
            float rs = 0.f;
#pragma unroll
            for (int j = 0; j < 4; j++) {
                float p = exp2f_fast(s[i][j] - mnew);
                s[i][j] = p; rs += p;
            }
            rs += __shfl_xor_sync(0xffffffffu, rs, 1);
            rs += __shfl_xor_sync(0xffffffffu, rs, 2);
            rs += __shfl_xor_sync(0xffffffffu, rs, 4);
            rs += __shfl_xor_sync(0xffffffffu, rs, 8);
            lrow[i] = lrow[i] * corr + rs;
            mrow[i] = mnew;
#pragma unroll
            for (int j = 0; j < 4; j++) o[i][j] *= corr;
        }

        __syncthreads();
#pragma unroll
        for (int j = 0; j < 4; j++) {
            const int kv = tx * 4 + j;
            const int g0 = ((2 * ty)     + tx) & 15;
            const int g1 = ((2 * ty + 1) + tx) & 15;
            float4 p0, p1;
            p0.x = s[0][j]; p0.y = s[1][j]; p0.z = s[2][j]; p0.w = s[3][j];
            p1.x = s[4][j]; p1.y = s[5][j]; p1.z = s[6][j]; p1.w = s[7][j];
            *reinterpret_cast<float4*>(&ksf[kv * 64 + g0 * 4]) = p0;
            *reinterpret_cast<float4*>(&ksf[kv * 64 + g1 * 4]) = p1;
        }
        __syncthreads();

#pragma unroll 4
        for (int k = 0; k < 64; k++) {
            float pa[8], vb[4];
            const int g0 = ((2 * ty)     + (k >> 2)) & 15;
            const int g1 = ((2 * ty + 1) + (k >> 2)) & 15;
            *(float4*)&pa[0] = *(const float4*)&ksf[k * 64 + g0 * 4];
            *(float4*)&pa[4] = *(const float4*)&ksf[k * 64 + g1 * 4];
            *(float4*)&vb[0] = *(const float4*)&Vs[k][tx * 4];
#pragma unroll
            for (int i = 0; i < 8; i++)
#pragma unroll
                for (int j = 0; j < 4; j++) o[i][j] = fmaf(pa[i], vb[j], o[i][j]);
        }
    }

#pragma unroll
    for (int i = 0; i < 8; i++) {
        float inv = 1.f / lrow[i];
        int n = q0 + ty * 8 + i;
        float4 v;
        v.x = o[i][0] * inv; v.y = o[i][1] * inv;
        v.z = o[i][2] * inv; v.w = o[i][3] * inv;
        *reinterpret_cast<float4*>(
            g_AttO + (size_t)(b * SEQ + n) * HDIM + h * HD + tx * 4) = v;
    }
}

// ---------------------------------------------------------------------------
extern "C" void kernel_launch(void* const* d_in, const int* in_sizes, int n_in,
                              void* d_out, int out_size)
{
    const float* x     = (const float*)d_in[0];
    const float* w_qkv = (const float*)d_in[1];
    const float* b_qkv = (const float*)d_in[2];
    const float* w_out = (const float*)d_in[3];
    const float* b_out = (const float*)d_in[4];
    float* out = (float*)d_out;
    (void)in_sizes; (void)n_in; (void)out_size;

    dim3 g1(QKVN / 128, MTOK / 64);                  // 18 x 256 blocks
    sgemm_kernel<0><<<g1, 128>>>(x, w_qkv, b_qkv, nullptr, QKVN);

    dim3 g2(SEQ / 64, NHEADS, BATCH);                // 16 x 12 x 16 blocks
    attn_kernel<<<g2, 128>>>();

    dim3 g3(HDIM / 128, MTOK / 64);                  // 6 x 256 blocks
    sgemm_kernel<1><<<g3, 128>>>(g_AttO, w_out, b_out, out, HDIM);
}

// round 15
// speedup vs baseline: 1.0975x; 1.0855x over previous
#include <cuda_runtime.h>

#define BATCH  16
#define SEQ    1024
#define HDIM   768
#define NHEADS 12
#define HD     64
#define MTOK   (BATCH*SEQ)      /* 16384 */
#define QKVN   (3*HDIM)         /* 2304  */

// ------------------------- device scratch (no alloc rule) -------------------
__device__ __align__(256) float g_Q[BATCH*NHEADS*SEQ*HD];
__device__ __align__(256) float g_K[BATCH*NHEADS*SEQ*HD];
__device__ __align__(256) float g_V[BATCH*NHEADS*SEQ*HD];
__device__ __align__(256) float g_AttO[MTOK*HDIM];

// Fast exp2 on (-inf, 0]: degree-6 poly + exponent bits. No MUFU.
__device__ __forceinline__ float exp2f_fast(float x) {
    x = fmaxf(x, -125.0f);
    float t = floorf(x);
    float f = x - t;
    float p = 1.5403530e-4f;
    p = fmaf(p, f, 1.3333558e-3f);
    p = fmaf(p, f, 9.6181291e-3f);
    p = fmaf(p, f, 5.5504109e-2f);
    p = fmaf(p, f, 2.4022651e-1f);
    p = fmaf(p, f, 6.9314718e-1f);
    p = fmaf(p, f, 1.0f);
    int e = (int)t;
    return p * __int_as_float((e + 127) << 23);
}

// ---------------------------------------------------------------------------
// SGEMM: C[M,Ncols] = A[M,768] @ W[768,Ncols] + bias
// 64x128 CTA tile, 128 threads, 8x8 microtile with SPLIT B columns:
// cols {tx*4..+3} and {64+tx*4..+3}  -> B-fragment LDS.128 at 16B stride =
// conflict-free per 8-lane phase (was 4-way conflicted at tx*8 / 32B stride).
// KB=16 double-buffered with register prefetch.
// MODE 0: A = x, scatter into g_Q/g_K/g_V head-major. MODE 1: dense out.
// ---------------------------------------------------------------------------
#define KB     16
#define NCHUNK (HDIM / KB)      /* 48 */

template<int MODE>
__global__ __launch_bounds__(128)
void sgemm_kernel(const float* __restrict__ A, const float* __restrict__ W,
                  const float* __restrict__ bias, float* __restrict__ out,
                  int Ncols)
{
    __shared__ float As[2][KB][68];    // transposed [k][m], padded
    __shared__ float Bs[2][KB][128];   // natural [k][n]

    const int tid = threadIdx.x;
    const int m0  = blockIdx.y * 64;
    const int c0  = blockIdx.x * 128;
    const int ty  = tid >> 4;          // 0..7  -> rows ty*8..
    const int tx  = tid & 15;          // 0..15 -> col chunks tx*4 and 64+tx*4

    const float* Ap = (MODE == 0) ? A : g_AttO;

    // loader lanes: A = 2 float4 (one row, 16 k), B = 4 float4 (4 rows)
    const int ar = tid >> 1;           // 0..63
    const int ac = (tid & 1) * 8;      // 0 or 8
    const int br = tid >> 5;           // 0..3  (+4,+8,+12)
    const int bc = (tid & 31) * 4;     // 0..124

    float acc[8][8];
#pragma unroll
    for (int i = 0; i < 8; i++)
#pragma unroll
        for (int j = 0; j < 8; j++) acc[i][j] = 0.f;

    // ---- prologue: chunk 0 ----
    {
        float4 a0 = *reinterpret_cast<const float4*>(Ap + (size_t)(m0 + ar) * HDIM + ac);
        float4 a1 = *reinterpret_cast<const float4*>(Ap + (size_t)(m0 + ar) * HDIM + ac + 4);
        As[0][ac + 0][ar] = a0.x; As[0][ac + 1][ar] = a0.y;
        As[0][ac + 2][ar] = a0.z; As[0][ac + 3][ar] = a0.w;
        As[0][ac + 4][ar] = a1.x; As[0][ac + 5][ar] = a1.y;
        As[0][ac + 6][ar] = a1.z; As[0][ac + 7][ar] = a1.w;
#pragma unroll
        for (int r = 0; r < 4; r++) {
            float4 bv = *reinterpret_cast<const float4*>(
                W + (size_t)(br + r * 4) * Ncols + c0 + bc);
            *reinterpret_cast<float4*>(&Bs[0][br + r * 4][bc]) = bv;
        }
    }
    __syncthreads();

    for (int ch = 0; ch < NCHUNK; ch++) {
        const int buf = ch & 1;
        float4 a0, a1, b0, b1, b2, b3;
        if (ch + 1 < NCHUNK) {
            const int kb = (ch + 1) * KB;
            a0 = *reinterpret_cast<const float4*>(Ap + (size_t)(m0 + ar) * HDIM + kb + ac);
            a1 = *reinterpret_cast<const float4*>(Ap + (size_t)(m0 + ar) * HDIM + kb + ac + 4);
            b0 = *reinterpret_cast<const float4*>(W + (size_t)(kb + br +  0) * Ncols + c0 + bc);
            b1 = *reinterpret_cast<const float4*>(W + (size_t)(kb + br +  4) * Ncols + c0 + bc);
            b2 = *reinterpret_cast<const float4*>(W + (size_t)(kb + br +  8) * Ncols + c0 + bc);
            b3 = *reinterpret_cast<const float4*>(W + (size_t)(kb + br + 12) * Ncols + c0 + bc);
        }

#pragma unroll
        for (int k = 0; k < KB; k++) {
            float a[8], b[8];
            *(float4*)&a[0] = *(const float4*)&As[buf][k][ty * 8];
            *(float4*)&a[4] = *(const float4*)&As[buf][k][ty * 8 + 4];
            *(float4*)&b[0] = *(const float4*)&Bs[buf][k][tx * 4];        // conflict-free
            *(float4*)&b[4] = *(const float4*)&Bs[buf][k][64 + tx * 4];   // conflict-free
#pragma unroll
            for (int i = 0; i < 8; i++)
#pragma unroll
                for (int j = 0; j < 8; j++) acc[i][j] = fmaf(a[i], b[j], acc[i][j]);
        }

        if (ch + 1 < NCHUNK) {
            const int nb = buf ^ 1;
            As[nb][ac + 0][ar] = a0.x; As[nb][ac + 1][ar] = a0.y;
            As[nb][ac + 2][ar] = a0.z; As[nb][ac + 3][ar] = a0.w;
            As[nb][ac + 4][ar] = a1.x; As[nb][ac + 5][ar] = a1.y;
            As[nb][ac + 6][ar] = a1.z; As[nb][ac + 7][ar] = a1.w;
            *reinterpret_cast<float4*>(&Bs[nb][br +  0][bc]) = b0;
            *reinterpret_cast<float4*>(&Bs[nb][br +  4][bc]) = b1;
            *reinterpret_cast<float4*>(&Bs[nb][br +  8][bc]) = b2;
            *reinterpret_cast<float4*>(&Bs[nb][br + 12][bc]) = b3;
        }
        __syncthreads();
    }

    // ---- epilogue: two 4-col chunks per row ----
    const int cb0 = c0 + tx * 4;
    const int cb1 = c0 + 64 + tx * 4;
    if (MODE == 0) {
        const int part = c0 / HDIM;                      // 128 block never crosses parts
        float* dst = (part == 0) ? g_Q : (part == 1 ? g_K : g_V);
        const int cc0 = cb0 - part * HDIM, cc1 = cb1 - part * HDIM;
        const int h0 = cc0 >> 6, d0 = cc0 & 63;
        const int h1 = cc1 >> 6, d1 = cc1 & 63;
        const float4 bv0 = *reinterpret_cast<const float4*>(bias + cb0);
        const float4 bv1 = *reinterpret_cast<const float4*>(bias + cb1);
#pragma unroll
        for (int i = 0; i < 8; i++) {
            int m = m0 + ty * 8 + i;
            int bi = m >> 10, n = m & (SEQ - 1);
            float4 v0, v1;
            v0.x = acc[i][0] + bv0.x; v0.y = acc[i][1] + bv0.y;
            v0.z = acc[i][2] + bv0.z; v0.w = acc[i][3] + bv0.w;
            v1.x = acc[i][4] + bv1.x; v1.y = acc[i][5] + bv1.y;
            v1.z = acc[i][6] + bv1.z; v1.w = acc[i][7] + bv1.w;
            *reinterpret_cast<float4*>(
                dst + ((size_t)(bi * NHEADS + h0) * SEQ + n) * HD + d0) = v0;
            *reinterpret_cast<float4*>(
                dst + ((size_t)(bi * NHEADS + h1) * SEQ + n) * HD + d1) = v1;
        }
    } else {
        const float4 bv0 = *reinterpret_cast<const float4*>(bias + cb0);
        const float4 bv1 = *reinterpret_cast<const float4*>(bias + cb1);
#pragma unroll
        for (int i = 0; i < 8; i++) {
            int m = m0 + ty * 8 + i;
            float4 v0, v1;
            v0.x = acc[i][0] + bv0.x; v0.y = acc[i][1] + bv0.y;
            v0.z = acc[i][2] + bv0.z; v0.w = acc[i][3] + bv0.w;
            v1.x = acc[i][4] + bv1.x; v1.y = acc[i][5] + bv1.y;
            v1.z = acc[i][6] + bv1.z; v1.w = acc[i][7] + bv1.w;
            *reinterpret_cast<float4*>(out + (size_t)m * HDIM + cb0) = v0;
            *reinterpret_cast<float4*>(out + (size_t)m * HDIM + cb1) = v1;
        }
    }
}

// ---------------------------------------------------------------------------
// Flash attention (round-10/11 verified, FROZEN): 128 threads, 64x64 tile,
// 8x4 microtile, MUFU-free softmax, swizzled K/P staging.
// ---------------------------------------------------------------------------
__global__ __launch_bounds__(128)
void attn_kernel()
{
    __shared__ float Qs[64][64];
    __shared__ float Ks[64][64];
    __shared__ float Vs[64][64];

    const int tid = threadIdx.x;
    const int tx  = tid & 15;
    const int ty  = tid >> 4;
    const int b   = blockIdx.z, h = blockIdx.y;
    const int q0  = blockIdx.x * 64;

    const float* Qg = g_Q + (size_t)((b * NHEADS + h) * SEQ + q0) * HD;
    const float* Kg = g_K + (size_t)((b * NHEADS + h) * SEQ) * HD;
    const float* Vg = g_V + (size_t)((b * NHEADS + h) * SEQ) * HD;

    const float QSCALE = 0.125f * 1.4426950408889634f;
    float* ksf = &Ks[0][0];

    for (int f = tid; f < 1024; f += 128) {
        int r = f >> 4, c4 = (f & 15) << 2;
        float4 v = *reinterpret_cast<const float4*>(Qg + r * HD + c4);
        Qs[c4 + 0][r] = v.x * QSCALE; Qs[c4 + 1][r] = v.y * QSCALE;
        Qs[c4 + 2][r] = v.z * QSCALE; Qs[c4 + 3][r] = v.w * QSCALE;
    }

    float o[8][4], mrow[8], lrow[8];
#pragma unroll
    for (int i = 0; i < 8; i++) {
        mrow[i] = -1e30f; lrow[i] = 0.f;
#pragma unroll
        for (int j = 0; j < 4; j++) o[i][j] = 0.f;
    }

    for (int kt = 0; kt < SEQ / 64; kt++) {
        __syncthreads();
        const float* Kt = Kg + (size_t)kt * 64 * HD;
        const float* Vt = Vg + (size_t)kt * 64 * HD;
        for (int f = tid; f < 1024; f += 128) {
            int r  = f >> 4;
            int c4 = (f & 15) << 2;
            float4 kv = *reinterpret_cast<const float4*>(Kt + r * HD + c4);
            int sg   = ((r >> 2) + (c4 >> 2)) & 15;
            int base = sg * 4 + (r & 3);
            ksf[(c4 + 0) * 64 + base] = kv.x;
            ksf[(c4 + 1) * 64 + base] = kv.y;
            ksf[(c4 + 2) * 64 + base] = kv.z;
            ksf[(c4 + 3) * 64 + base] = kv.w;
            float4 vv = *reinterpret_cast<const float4*>(Vt + r * HD + c4);
            *reinterpret_cast<float4*>(&Vs[r][c4]) = vv;
        }
        __syncthreads();

        float s[8][4];
#pragma unroll
        for (int i = 0; i < 8; i++)
#pragma unroll
            for (int j = 0; j < 4; j++) s[i][j] = 0.f;
#pragma unroll 4
        for (int d = 0; d < 64; d++) {
            float qa[8], kb[4];
            *(float4*)&qa[0] = *(const float4*)&Qs[d][ty * 8];
            *(float4*)&qa[4] = *(const float4*)&Qs[d][ty * 8 + 4];
            int g = (tx + (d >> 2)) & 15;
            *(float4*)&kb[0] = *(const float4*)&ksf[d * 64 + g * 4];
#pragma unroll
            for (int i = 0; i < 8; i++)
#pragma unroll
                for (int j = 0; j < 4; j++) s[i][j] = fmaf(qa[i], kb[j], s[i][j]);
        }

#pragma unroll
        for (int i = 0; i < 8; i++) {
            float mx = fmaxf(fmaxf(s[i][0], s[i][1]), fmaxf(s[i][2], s[i][3]));
            mx = fmaxf(mx, __shfl_xor_sync(0xffffffffu, mx, 1));
            mx = fmaxf(mx, __shfl_xor_sync(0xffffffffu, mx, 2));
            mx = fmaxf(mx, __shfl_xor_sync(0xffffffffu, mx, 4));
            mx = fmaxf(mx, __shfl_xor_sync(0xffffffffu, mx, 8));
            float mnew = fmaxf(mrow[i], mx);
            float corr = exp2f_fast(mrow[i] - mnew);
            float rs = 0.f;
#pragma unroll
            for (int j = 0; j < 4; j++) {
                float p = exp2f_fast(s[i][j] - mnew);
                s[i][j] = p; rs += p;
            }
            rs += __shfl_xor_sync(0xffffffffu, rs, 1);
            rs += __shfl_xor_sync(0xffffffffu, rs, 2);
            rs += __shfl_xor_sync(0xffffffffu, rs, 4);
            rs += __shfl_xor_sync(0xffffffffu, rs, 8);
            lrow[i] = lrow[i] * corr + rs;
            mrow[i] = mnew;
#pragma unroll
            for (int j = 0; j < 4; j++) o[i][j] *= corr;
        }

        __syncthreads();
#pragma unroll
        for (int j = 0; j < 4; j++) {
            const int kv = tx * 4 + j;
            const int g0 = ((2 * ty)     + tx) & 15;
            const int g1 = ((2 * ty + 1) + tx) & 15;
            float4 p0, p1;
            p0.x = s[0][j]; p0.y = s[1][j]; p0.z = s[2][j]; p0.w = s[3][j];
            p1.x = s[4][j]; p1.y = s[5][j]; p1.z = s[6][j]; p1.w = s[7][j];
            *reinterpret_cast<float4*>(&ksf[kv * 64 + g0 * 4]) = p0;
            *reinterpret_cast<float4*>(&ksf[kv * 64 + g1 * 4]) = p1;
        }
        __syncthreads();

#pragma unroll 4
        for (int k = 0; k < 64; k++) {
            float pa[8], vb[4];
            const int g0 = ((2 * ty)     + (k >> 2)) & 15;
            const int g1 = ((2 * ty + 1) + (k >> 2)) & 15;
            *(float4*)&pa[0] = *(const float4*)&ksf[k * 64 + g0 * 4];
            *(float4*)&pa[4] = *(const float4*)&ksf[k * 64 + g1 * 4];
            *(float4*)&vb[0] = *(const float4*)&Vs[k][tx * 4];
#pragma unroll
            for (int i = 0; i < 8; i++)
#pragma unroll
                for (int j = 0; j < 4; j++) o[i][j] = fmaf(pa[i], vb[j], o[i][j]);
        }
    }

#pragma unroll
    for (int i = 0; i < 8; i++) {
        float inv = 1.f / lrow[i];
        int n = q0 + ty * 8 + i;
        float4 v;
        v.x = o[i][0] * inv; v.y = o[i][1] * inv;
        v.z = o[i][2] * inv; v.w = o[i][3] * inv;
        *reinterpret_cast<float4*>(
            g_AttO + (size_t)(b * SEQ + n) * HDIM + h * HD + tx * 4) = v;
    }
}

// ---------------------------------------------------------------------------
extern "C" void kernel_launch(void* const* d_in, const int* in_sizes, int n_in,
                              void* d_out, int out_size)
{
    const float* x     = (const float*)d_in[0];
    const float* w_qkv = (const float*)d_in[1];
    const float* b_qkv = (const float*)d_in[2];
    const float* w_out = (const float*)d_in[3];
    const float* b_out = (const float*)d_in[4];
    float* out = (float*)d_out;
    (void)in_sizes; (void)n_in; (void)out_size;

    dim3 g1(QKVN / 128, MTOK / 64);                  // 18 x 256 blocks
    sgemm_kernel<0><<<g1, 128>>>(x, w_qkv, b_qkv, nullptr, QKVN);

    dim3 g2(SEQ / 64, NHEADS, BATCH);                // 16 x 12 x 16 blocks
    attn_kernel<<<g2, 128>>>();

    dim3 g3(HDIM / 128, MTOK / 64);                  // 6 x 256 blocks
    sgemm_kernel<1><<<g3, 128>>>(g_AttO, w_out, b_out, out, HDIM);
}